// round 7
// baseline (speedup 1.0000x reference)
#include <cuda_runtime.h>
#include <cuda_fp16.h>
#include <cstdint>

// ---------------- model constants ----------------
#define BSZ      512
#define NCH      129
#define NT       250
#define DINNER   256
#define DSTATE   16
#define NHEADS   4
#define CONVDIM  288
#define DPROJ    548
#define EPSV     1e-5f

// GEMM tiling: K = 128 (MMA) + 1 (rank-1 epilogue fixup)
#define TM     128
#define TN     72
#define TK     128
#define NJC    8
#define NKK    8
#define PITCHB 272
#define SPITCH 76

// ---------------- device scratch ----------------
__device__ float g_W[DPROJ * NCH];
__device__ float g_bias[DPROJ];
__device__ float g_v[DINNER];
__device__ float g_zxbcdt[(size_t)BSZ * NT * DPROJ];
__device__ __align__(16) __half g_Wh[NJC * TN * TK];
__device__ float g_Wcol[576];
__device__ float g_biasP[576];
__device__ __align__(8) float2 g_part[(size_t)BSZ * NT * NHEADS];  // (ss, p)

// ---------------- GEMM smem layout (bytes) ----------------
#define SM_AH    0                      // 128*272 = 34816
#define SM_BH    34816                  // 72*272  = 19584
#define SM_X128  54400
#define SM_W128  54912
#define SM_BIAS  55200
#define SMEM_SZ  55488

// ---------------- packed f32x2 helpers ----------------
typedef unsigned long long ull;
__device__ __forceinline__ ull dup2(float v) {
    ull r; asm("mov.b64 %0, {%1, %1};" : "=l"(r) : "f"(v)); return r;
}
__device__ __forceinline__ ull pack2(float lo, float hi) {
    ull r; asm("mov.b64 %0, {%1, %2};" : "=l"(r) : "f"(lo), "f"(hi)); return r;
}
__device__ __forceinline__ ull ffma2(ull a, ull b, ull c) {
    ull d; asm("fma.rn.f32x2 %0, %1, %2, %3;" : "=l"(d) : "l"(a), "l"(b), "l"(c)); return d;
}
__device__ __forceinline__ ull fmul2(ull a, ull b) {
    ull d; asm("mul.rn.f32x2 %0, %1, %2;" : "=l"(d) : "l"(a), "l"(b)); return d;
}
__device__ __forceinline__ ull fadd2(ull a, ull b) {
    ull d; asm("add.rn.f32x2 %0, %1, %2;" : "=l"(d) : "l"(a), "l"(b)); return d;
}
__device__ __forceinline__ float2 unpk2(ull v) {
    float2 f; asm("mov.b64 {%0, %1}, %2;" : "=f"(f.x), "=f"(f.y) : "l"(v)); return f;
}

// ---------------- mma / ldmatrix (base sm_103 PTX) ----------------
__device__ __forceinline__ void mma16816(float* d, const uint32_t* a, const uint32_t* b) {
    asm volatile(
        "mma.sync.aligned.m16n8k16.row.col.f32.f16.f16.f32 "
        "{%0,%1,%2,%3}, {%4,%5,%6,%7}, {%8,%9}, {%0,%1,%2,%3};"
        : "+f"(d[0]), "+f"(d[1]), "+f"(d[2]), "+f"(d[3])
        : "r"(a[0]), "r"(a[1]), "r"(a[2]), "r"(a[3]), "r"(b[0]), "r"(b[1]));
}
__device__ __forceinline__ void ldsm4(uint32_t* r, uint32_t addr) {
    asm volatile("ldmatrix.sync.aligned.m8n8.x4.shared.b16 {%0,%1,%2,%3}, [%4];"
        : "=r"(r[0]), "=r"(r[1]), "=r"(r[2]), "=r"(r[3]) : "r"(addr));
}
__device__ __forceinline__ void ldsm2(uint32_t* r, uint32_t addr) {
    asm volatile("ldmatrix.sync.aligned.m8n8.x2.shared.b16 {%0,%1}, [%2];"
        : "=r"(r[0]), "=r"(r[1]) : "r"(addr));
}
__device__ __forceinline__ uint32_t smem_u32(const void* p) {
    uint32_t a;
    asm("{ .reg .u64 t; cvta.to.shared.u64 t, %1; cvt.u32.u64 %0, t; }" : "=r"(a) : "l"(p));
    return a;
}

// =====================================================================
// prep1: fused weights
// =====================================================================
__global__ void prep1_kernel(const float* __restrict__ in_proj_w,
                             const float* __restrict__ mixer_w,
                             const float* __restrict__ mixer_b,
                             const float* __restrict__ out_proj_w,
                             const float* __restrict__ head_w) {
    int idx = blockIdx.x * blockDim.x + threadIdx.x;
    const int NW = DPROJ * NCH;
    if (idx < NW) {
        int j = idx / NCH, c = idx - j * NCH;
        float a0 = 0.f, a1 = 0.f, a2 = 0.f, a3 = 0.f;
        #pragma unroll 8
        for (int d = 0; d < 128; d += 4) {
            a0 = fmaf(in_proj_w[j * 128 + d + 0], mixer_w[(d + 0) * NCH + c], a0);
            a1 = fmaf(in_proj_w[j * 128 + d + 1], mixer_w[(d + 1) * NCH + c], a1);
            a2 = fmaf(in_proj_w[j * 128 + d + 2], mixer_w[(d + 2) * NCH + c], a2);
            a3 = fmaf(in_proj_w[j * 128 + d + 3], mixer_w[(d + 3) * NCH + c], a3);
        }
        g_W[idx] = (a0 + a1) + (a2 + a3);
    } else if (idx < NW + DPROJ) {
        int j = idx - NW;
        float acc = 0.f;
        #pragma unroll 4
        for (int d = 0; d < 128; d++)
            acc = fmaf(in_proj_w[j * 128 + d], mixer_b[d], acc);
        g_bias[j] = acc;
    } else if (idx < NW + DPROJ + DINNER) {
        int i = idx - NW - DPROJ;
        float acc = 0.f;
        #pragma unroll 4
        for (int d = 0; d < 128; d++)
            acc = fmaf(out_proj_w[d * DINNER + i], head_w[d], acc);
        g_v[i] = acc;
    }
}

// =====================================================================
// prep2: W (k<128) -> fp16 chunk tiles; pad Wcol/bias
// =====================================================================
__global__ void prep2_kernel() {
    int idx = blockIdx.x * blockDim.x + threadIdx.x;
    const int NH = NJC * TN * TK;
    if (idx < NH) {
        int k = idx & 127;
        int t = idx >> 7;
        int n = t % TN;
        int jc = t / TN;
        int j = jc * TN + n;
        float val = (j < DPROJ) ? g_W[j * NCH + k] : 0.f;
        g_Wh[idx] = __float2half(val);
    } else if (idx < NH + 576) {
        int j = idx - NH;
        g_Wcol[j] = (j < DPROJ) ? g_W[j * NCH + 128] : 0.f;
    } else if (idx < NH + 1152) {
        int j = idx - NH - 576;
        g_biasP[j] = (j < DPROJ) ? g_bias[j] : 0.f;
    }
}

// =====================================================================
// gemm_mma: SINGLE-pass fp16 GEMM (x fp16 vs W fp16, k=128 fixup fp32)
// =====================================================================
__global__ void __launch_bounds__(256, 2) gemm_mma(const float* __restrict__ x) {
    extern __shared__ __align__(16) unsigned char sm[];
    const uint32_t sbase = smem_u32(sm);
    const int tid = threadIdx.x;
    const int wid = tid >> 5, lane = tid & 31;
    const int gid = lane >> 2, tig = lane & 3;
    const int tt = blockIdx.x, jc = blockIdx.y, b = blockIdx.z;
    const int t0 = tt * TM;

    {
        const unsigned char* src = (const unsigned char*)(g_Wh + (size_t)jc * (TN * TK));
        for (int i = tid; i < TN * 16; i += 256) {
            int n = i >> 4, q = i & 15;
            *(uint4*)(sm + SM_BH + n * PITCHB + q * 16) = *(const uint4*)(src + n * 256 + q * 16);
        }
    }
    {
        const float* xb = x + (size_t)b * (NCH * NT);
        for (int i = tid; i < 64 * TM; i += 256) {
            int cp = i >> 7, m = i & (TM - 1);
            int t = t0 + m;
            int c0 = 2 * cp;
            float v0 = (t < NT) ? xb[(size_t)c0 * NT + t] : 0.f;
            float v1 = (t < NT) ? xb[(size_t)(c0 + 1) * NT + t] : 0.f;
            uint32_t off = (uint32_t)m * PITCHB + (uint32_t)cp * 4;
            *(__half2*)(sm + SM_AH + off) = __half2{__float2half(v0), __float2half(v1)};
        }
    }
    if (tid < 128) {
        int t = t0 + tid;
        const float* xb = x + (size_t)b * (NCH * NT);
        *(float*)(sm + SM_X128 + tid * 4) = (t < NT) ? xb[(size_t)128 * NT + t] : 0.f;
        if (tid < TN) {
            *(float*)(sm + SM_W128 + tid * 4) = g_Wcol[jc * TN + tid];
            *(float*)(sm + SM_BIAS + tid * 4) = g_biasP[jc * TN + tid];
        }
    }
    __syncthreads();

    float acc[9][4];
    #pragma unroll
    for (int ni = 0; ni < 9; ni++)
        #pragma unroll
        for (int q = 0; q < 4; q++) acc[ni][q] = 0.f;

    const uint32_t aOff = (uint32_t)(wid * 16 + (lane & 15)) * PITCHB + (uint32_t)(lane >> 4) * 16;
    const uint32_t bOff = (uint32_t)(lane & 15) * PITCHB + (uint32_t)(lane >> 4) * 16;
    const uint32_t b2Off = (uint32_t)(64 + (lane & 7)) * PITCHB + (uint32_t)((lane >> 3) & 1) * 16;

    const uint32_t Ah = sbase + SM_AH + aOff;
    const uint32_t Bb = sbase + SM_BH + bOff;
    const uint32_t Bb2 = sbase + SM_BH + b2Off;

    #pragma unroll
    for (int kk = 0; kk < NKK; kk++) {
        uint32_t ah[4];
        ldsm4(ah, Ah + kk * 32);
        #pragma unroll
        for (int q = 0; q < 4; q++) {
            uint32_t bb[4];
            ldsm4(bb, Bb + (uint32_t)(q * 16) * PITCHB + kk * 32);
            uint32_t f0[2] = { bb[0], bb[2] };
            uint32_t f1[2] = { bb[1], bb[3] };
            mma16816(acc[2 * q],     ah, f0);
            mma16816(acc[2 * q + 1], ah, f1);
        }
        uint32_t b2[2];
        ldsm2(b2, Bb2 + kk * 32);
        mma16816(acc[8], ah, b2);
    }

    __syncthreads();
    float* stage = (float*)sm;
    {
        int r = wid * 16 + gid;
        #pragma unroll
        for (int ni = 0; ni < 9; ni++) {
            int c = ni * 8 + 2 * tig;
            *(float2*)(stage + r * SPITCH + c) = make_float2(acc[ni][0], acc[ni][1]);
            *(float2*)(stage + (r + 8) * SPITCH + c) = make_float2(acc[ni][2], acc[ni][3]);
        }
    }
    __syncthreads();

    const float* xs128 = (const float*)(sm + SM_X128);
    const float* sW = (const float*)(sm + SM_W128);
    const float* sBs = (const float*)(sm + SM_BIAS);
    for (int i = tid; i < TM * (TN / 4); i += 256) {
        int row = i / (TN / 4), q = i % (TN / 4);
        int t = t0 + row;
        int j = jc * TN + 4 * q;
        if (t < NT && j + 3 < DPROJ) {
            const float* sp = stage + row * SPITCH + 4 * q;
            float xk = xs128[row];
            float4 o;
            o.x = fmaf(xk, sW[4 * q + 0], sp[0] + sBs[4 * q + 0]);
            o.y = fmaf(xk, sW[4 * q + 1], sp[1] + sBs[4 * q + 1]);
            o.z = fmaf(xk, sW[4 * q + 2], sp[2] + sBs[4 * q + 2]);
            o.w = fmaf(xk, sW[4 * q + 3], sp[3] + sBs[4 * q + 3]);
            *(float4*)(g_zxbcdt + ((size_t)b * NT + t) * DPROJ + j) = o;
        }
    }
}

// =====================================================================
// scan: one warp per (b, h). 2048 CTAs of 32 threads. No block barriers.
//   every lane: conv+silu+scan for x channels {h*64+2*lane, +1}, z gate
//   lanes 0-15: also produce shared B/C conv (channels 256+2*lane)
//   lane 16   : also produce dt/dA for head h
//   per-t RMS partials (sum g^2, sum g*w) -> g_part[b][t][h]
// =====================================================================
__global__ void __launch_bounds__(32, 32)
scan_kernel(const float* __restrict__ conv_w, const float* __restrict__ conv_b,
            const float* __restrict__ dt_bias, const float* __restrict__ A_log,
            const float* __restrict__ Dp, const float* __restrict__ norm_w) {
    const int bx = blockIdx.x;
    const int b = bx >> 2, h = bx & 3;
    const int lane = threadIdx.x;

    __shared__ __align__(8) ull sBC[2][32];     // [buf][0..15 B dup2, 16..31 C dup2]
    __shared__ float sdA[2], sdt[2];

    // own x channels
    const int cx = h * 64 + 2 * lane;
    ull wx0 = pack2(conv_w[cx * 4 + 0], conv_w[(cx + 1) * 4 + 0]);
    ull wx1 = pack2(conv_w[cx * 4 + 1], conv_w[(cx + 1) * 4 + 1]);
    ull wx2 = pack2(conv_w[cx * 4 + 2], conv_w[(cx + 1) * 4 + 2]);
    ull wx3 = pack2(conv_w[cx * 4 + 3], conv_w[(cx + 1) * 4 + 3]);
    ull cbx = pack2(conv_b[cx], conv_b[cx + 1]);
    ull hx1 = 0ULL, hx2 = 0ULL, hx3 = 0ULL;

    // B/C producer params (lanes 0-15): conv channels 256+2*lane
    ull wb0 = 0, wb1 = 0, wb2 = 0, wb3 = 0, cbb = 0;
    if (lane < 16) {
        const int cb = 256 + 2 * lane;
        wb0 = pack2(conv_w[cb * 4 + 0], conv_w[(cb + 1) * 4 + 0]);
        wb1 = pack2(conv_w[cb * 4 + 1], conv_w[(cb + 1) * 4 + 1]);
        wb2 = pack2(conv_w[cb * 4 + 2], conv_w[(cb + 1) * 4 + 2]);
        wb3 = pack2(conv_w[cb * 4 + 3], conv_w[(cb + 1) * 4 + 3]);
        cbb = pack2(conv_b[cb], conv_b[cb + 1]);
    }
    ull hb1 = 0ULL, hb2 = 0ULL, hb3 = 0ULL;

    float dtb = 0.f, Aneg = 0.f;
    if (lane == 16) { dtb = dt_bias[h]; Aneg = -expf(A_log[h]); }

    const float nw0 = norm_w[cx] * g_v[cx];
    const float nw1 = norm_w[cx + 1] * g_v[cx + 1];
    const ull D2 = dup2(Dp[h]);

    ull s2[DSTATE];
    #pragma unroll
    for (int n = 0; n < DSTATE; n++) s2[n] = 0ULL;

    const float* row = g_zxbcdt + (size_t)b * NT * DPROJ;
    float2* part = g_part + ((size_t)b * NT) * NHEADS + h;

    // prefetch t=0
    ull rawx = *(const ull*)(row + 256 + cx);
    float2 z2 = *(const float2*)(row + cx);
    ull rawb = (lane < 16) ? *(const ull*)(row + 512 + 2 * lane) : 0ULL;
    float dtr = (lane == 16) ? row[544 + h] : 0.f;

    for (int t = 0; t < NT; t++) {
        const int buf = t & 1;

        // ---- producers ----
        if (lane < 16) {
            ull cv2 = ffma2(wb3, rawb, ffma2(wb2, hb1, ffma2(wb1, hb2, ffma2(wb0, hb3, cbb))));
            hb3 = hb2; hb2 = hb1; hb1 = rawb;
            float2 cv = unpk2(cv2);
            float c0 = __fdividef(cv.x, 1.f + __expf(-cv.x));
            float c1 = __fdividef(cv.y, 1.f + __expf(-cv.y));
            sBC[buf][2 * lane]     = dup2(c0);
            sBC[buf][2 * lane + 1] = dup2(c1);
        }
        if (lane == 16) {
            float rv = dtr + dtb;
            float dtv = (rv > 15.f) ? rv : __logf(1.f + __expf(rv));
            sdt[buf] = dtv;
            sdA[buf] = __expf(dtv * Aneg);
        }

        // ---- own conv + gates ----
        ull cvx = ffma2(wx3, rawx, ffma2(wx2, hx1, ffma2(wx1, hx2, ffma2(wx0, hx3, cbx))));
        hx3 = hx2; hx2 = hx1; hx1 = rawx;
        float2 cvf = unpk2(cvx);
        float cs0 = __fdividef(cvf.x, 1.f + __expf(-cvf.x));
        float cs1 = __fdividef(cvf.y, 1.f + __expf(-cvf.y));
        float gz0 = __fdividef(z2.x, 1.f + __expf(-z2.x));
        float gz1 = __fdividef(z2.y, 1.f + __expf(-z2.y));

        // ---- prefetch t+1 ----
        if (t + 1 < NT) {
            const float* rn = row + (size_t)(t + 1) * DPROJ;
            rawx = *(const ull*)(rn + 256 + cx);
            z2 = *(const float2*)(rn + cx);
            if (lane < 16) rawb = *(const ull*)(rn + 512 + 2 * lane);
            if (lane == 16) dtr = rn[544 + h];
        }
        __syncwarp();

        // ---- consume: state update + output ----
        float dtv = sdt[buf];
        ull dA2 = dup2(sdA[buf]);
        ull dx2 = pack2(dtv * cs0, dtv * cs1);
        ull ya = fmul2(D2, pack2(cs0, cs1));
        ull yb = 0ULL;
        const ull* Bt = &sBC[buf][0];
        const ull* Ct = &sBC[buf][16];
        #pragma unroll
        for (int n = 0; n < DSTATE; n += 2) {
            s2[n]     = ffma2(s2[n],     dA2, fmul2(dx2, Bt[n]));
            ya        = ffma2(s2[n],     Ct[n], ya);
            s2[n + 1] = ffma2(s2[n + 1], dA2, fmul2(dx2, Bt[n + 1]));
            yb        = ffma2(s2[n + 1], Ct[n + 1], yb);
        }
        float2 yy = unpk2(fadd2(ya, yb));
        float g0 = yy.x * gz0;
        float g1 = yy.y * gz1;
        float ss = fmaf(g0, g0, g1 * g1);
        float p  = fmaf(g0, nw0, g1 * nw1);
        #pragma unroll
        for (int o = 16; o > 0; o >>= 1) {
            ss += __shfl_xor_sync(0xffffffffu, ss, o);
            p  += __shfl_xor_sync(0xffffffffu, p, o);
        }
        if (lane == 0) part[(size_t)t * NHEADS] = make_float2(ss, p);
        __syncwarp();
    }
}

// =====================================================================
// combine: per-b rsqrt + pool + head
// =====================================================================
__global__ void __launch_bounds__(256)
combine_kernel(const float* __restrict__ head_b, float* __restrict__ out) {
    const int b = blockIdx.x;
    const int tid = threadIdx.x;
    const int lane = tid & 31, wid = tid >> 5;
    __shared__ float sred[8];

    float val = 0.f;
    if (tid < NT) {
        const float2* pp = g_part + ((size_t)b * NT + tid) * NHEADS;
        float2 p0 = pp[0], p1 = pp[1], p2 = pp[2], p3 = pp[3];
        float SS = (p0.x + p1.x) + (p2.x + p3.x);
        float P  = (p0.y + p1.y) + (p2.y + p3.y);
        val = P * rsqrtf(SS * (1.f / 256.f) + EPSV);
    }
    #pragma unroll
    for (int o = 16; o > 0; o >>= 1) val += __shfl_xor_sync(0xffffffffu, val, o);
    if (lane == 0) sred[wid] = val;
    __syncthreads();
    if (tid == 0) {
        float tot = 0.f;
        #pragma unroll
        for (int w = 0; w < 8; w++) tot += sred[w];
        out[b] = tot * (1.f / (float)NT) + head_b[0];
    }
}

// =====================================================================
// launch
// =====================================================================
extern "C" void kernel_launch(void* const* d_in, const int* in_sizes, int n_in,
                              void* d_out, int out_size) {
    const float* x          = (const float*)d_in[0];
    const float* mixer_w    = (const float*)d_in[1];
    const float* mixer_b    = (const float*)d_in[2];
    const float* in_proj_w  = (const float*)d_in[3];
    const float* conv_w     = (const float*)d_in[4];
    const float* conv_b     = (const float*)d_in[5];
    const float* dt_bias    = (const float*)d_in[6];
    const float* A_log      = (const float*)d_in[7];
    const float* Dvec       = (const float*)d_in[8];
    const float* norm_w     = (const float*)d_in[9];
    const float* out_proj_w = (const float*)d_in[10];
    const float* head_w     = (const float*)d_in[11];
    const float* head_b     = (const float*)d_in[12];
    float* out = (float*)d_out;

    {
        int total = DPROJ * NCH + DPROJ + DINNER;
        prep1_kernel<<<(total + 255) / 256, 256>>>(in_proj_w, mixer_w, mixer_b,
                                                   out_proj_w, head_w);
    }
    {
        int total = NJC * TN * TK + 1152;
        prep2_kernel<<<(total + 255) / 256, 256>>>();
    }
    {
        cudaFuncSetAttribute(gemm_mma,
                             cudaFuncAttributeMaxDynamicSharedMemorySize, SMEM_SZ);
        dim3 grid(2, NJC, BSZ);
        gemm_mma<<<grid, 256, SMEM_SZ>>>(x);
    }
    scan_kernel<<<BSZ * NHEADS, 32>>>(conv_w, conv_b, dt_bias, A_log, Dvec, norm_w);
    combine_kernel<<<BSZ, 256>>>(head_b, out);
}

// round 8
// speedup vs baseline: 1.6448x; 1.6448x over previous
#include <cuda_runtime.h>
#include <cuda_fp16.h>
#include <cstdint>

// ---------------- model constants ----------------
#define BSZ      512
#define NCH      129
#define NT       250
#define DINNER   256
#define DSTATE   16
#define NHEADS   4
#define CONVDIM  288
#define DPROJ    548
#define EPSV     1e-5f

// GEMM tiling: K = 128 (MMA) + 1 (rank-1 epilogue fixup)
#define TM     128
#define TN     72
#define TK     128
#define NJC    8
#define NKK    8
#define PITCHB 272
#define SPITCH 76

// ---------------- device scratch ----------------
__device__ float g_W[DPROJ * NCH];
__device__ float g_bias[DPROJ];
__device__ float g_v[DINNER];
__device__ float g_zxbcdt[(size_t)BSZ * NT * DPROJ];
__device__ __align__(16) __half g_Wh[NJC * TN * TK];
__device__ float g_Wcol[576];
__device__ float g_biasP[576];

// ---------------- GEMM smem layout (bytes) ----------------
#define SM_AH    0                      // 128*272 = 34816
#define SM_BH    34816                  // 72*272  = 19584
#define SM_X128  54400
#define SM_W128  54912
#define SM_BIAS  55200
#define SMEM_SZ  55488

// ---------------- packed f32x2 helpers ----------------
typedef unsigned long long ull;
__device__ __forceinline__ ull dup2(float v) {
    ull r; asm("mov.b64 %0, {%1, %1};" : "=l"(r) : "f"(v)); return r;
}
__device__ __forceinline__ ull pack2(float lo, float hi) {
    ull r; asm("mov.b64 %0, {%1, %2};" : "=l"(r) : "f"(lo), "f"(hi)); return r;
}
__device__ __forceinline__ ull ffma2(ull a, ull b, ull c) {
    ull d; asm("fma.rn.f32x2 %0, %1, %2, %3;" : "=l"(d) : "l"(a), "l"(b), "l"(c)); return d;
}
__device__ __forceinline__ ull fmul2(ull a, ull b) {
    ull d; asm("mul.rn.f32x2 %0, %1, %2;" : "=l"(d) : "l"(a), "l"(b)); return d;
}
__device__ __forceinline__ float2 unpk2(ull v) {
    float2 f; asm("mov.b64 {%0, %1}, %2;" : "=f"(f.x), "=f"(f.y) : "l"(v)); return f;
}

// ---------------- mma / ldmatrix (base sm_103 PTX) ----------------
__device__ __forceinline__ void mma16816(float* d, const uint32_t* a, const uint32_t* b) {
    asm volatile(
        "mma.sync.aligned.m16n8k16.row.col.f32.f16.f16.f32 "
        "{%0,%1,%2,%3}, {%4,%5,%6,%7}, {%8,%9}, {%0,%1,%2,%3};"
        : "+f"(d[0]), "+f"(d[1]), "+f"(d[2]), "+f"(d[3])
        : "r"(a[0]), "r"(a[1]), "r"(a[2]), "r"(a[3]), "r"(b[0]), "r"(b[1]));
}
__device__ __forceinline__ void ldsm4(uint32_t* r, uint32_t addr) {
    asm volatile("ldmatrix.sync.aligned.m8n8.x4.shared.b16 {%0,%1,%2,%3}, [%4];"
        : "=r"(r[0]), "=r"(r[1]), "=r"(r[2]), "=r"(r[3]) : "r"(addr));
}
__device__ __forceinline__ void ldsm2(uint32_t* r, uint32_t addr) {
    asm volatile("ldmatrix.sync.aligned.m8n8.x2.shared.b16 {%0,%1}, [%2];"
        : "=r"(r[0]), "=r"(r[1]) : "r"(addr));
}
__device__ __forceinline__ uint32_t smem_u32(const void* p) {
    uint32_t a;
    asm("{ .reg .u64 t; cvta.to.shared.u64 t, %1; cvt.u32.u64 %0, t; }" : "=r"(a) : "l"(p));
    return a;
}

// =====================================================================
// prep1: fused weights
// =====================================================================
__global__ void prep1_kernel(const float* __restrict__ in_proj_w,
                             const float* __restrict__ mixer_w,
                             const float* __restrict__ mixer_b,
                             const float* __restrict__ out_proj_w,
                             const float* __restrict__ head_w) {
    int idx = blockIdx.x * blockDim.x + threadIdx.x;
    const int NW = DPROJ * NCH;
    if (idx < NW) {
        int j = idx / NCH, c = idx - j * NCH;
        float a0 = 0.f, a1 = 0.f, a2 = 0.f, a3 = 0.f;
        #pragma unroll 8
        for (int d = 0; d < 128; d += 4) {
            a0 = fmaf(in_proj_w[j * 128 + d + 0], mixer_w[(d + 0) * NCH + c], a0);
            a1 = fmaf(in_proj_w[j * 128 + d + 1], mixer_w[(d + 1) * NCH + c], a1);
            a2 = fmaf(in_proj_w[j * 128 + d + 2], mixer_w[(d + 2) * NCH + c], a2);
            a3 = fmaf(in_proj_w[j * 128 + d + 3], mixer_w[(d + 3) * NCH + c], a3);
        }
        g_W[idx] = (a0 + a1) + (a2 + a3);
    } else if (idx < NW + DPROJ) {
        int j = idx - NW;
        float acc = 0.f;
        #pragma unroll 4
        for (int d = 0; d < 128; d++)
            acc = fmaf(in_proj_w[j * 128 + d], mixer_b[d], acc);
        g_bias[j] = acc;
    } else if (idx < NW + DPROJ + DINNER) {
        int i = idx - NW - DPROJ;
        float acc = 0.f;
        #pragma unroll 4
        for (int d = 0; d < 128; d++)
            acc = fmaf(out_proj_w[d * DINNER + i], head_w[d], acc);
        g_v[i] = acc;
    }
}

// =====================================================================
// prep2: W (k<128) -> fp16 chunk tiles; pad Wcol/bias
// =====================================================================
__global__ void prep2_kernel() {
    int idx = blockIdx.x * blockDim.x + threadIdx.x;
    const int NH = NJC * TN * TK;
    if (idx < NH) {
        int k = idx & 127;
        int t = idx >> 7;
        int n = t % TN;
        int jc = t / TN;
        int j = jc * TN + n;
        float val = (j < DPROJ) ? g_W[j * NCH + k] : 0.f;
        g_Wh[idx] = __float2half(val);
    } else if (idx < NH + 576) {
        int j = idx - NH;
        g_Wcol[j] = (j < DPROJ) ? g_W[j * NCH + 128] : 0.f;
    } else if (idx < NH + 1152) {
        int j = idx - NH - 576;
        g_biasP[j] = (j < DPROJ) ? g_bias[j] : 0.f;
    }
}

// =====================================================================
// gemm_mma: SINGLE-pass fp16 GEMM (x fp16 vs W fp16, k=128 fixup fp32)
// =====================================================================
__global__ void __launch_bounds__(256, 2) gemm_mma(const float* __restrict__ x) {
    extern __shared__ __align__(16) unsigned char sm[];
    const uint32_t sbase = smem_u32(sm);
    const int tid = threadIdx.x;
    const int wid = tid >> 5, lane = tid & 31;
    const int gid = lane >> 2, tig = lane & 3;
    const int tt = blockIdx.x, jc = blockIdx.y, b = blockIdx.z;
    const int t0 = tt * TM;

    {
        const unsigned char* src = (const unsigned char*)(g_Wh + (size_t)jc * (TN * TK));
        for (int i = tid; i < TN * 16; i += 256) {
            int n = i >> 4, q = i & 15;
            *(uint4*)(sm + SM_BH + n * PITCHB + q * 16) = *(const uint4*)(src + n * 256 + q * 16);
        }
    }
    {
        const float* xb = x + (size_t)b * (NCH * NT);
        for (int i = tid; i < 64 * TM; i += 256) {
            int cp = i >> 7, m = i & (TM - 1);
            int t = t0 + m;
            int c0 = 2 * cp;
            float v0 = (t < NT) ? xb[(size_t)c0 * NT + t] : 0.f;
            float v1 = (t < NT) ? xb[(size_t)(c0 + 1) * NT + t] : 0.f;
            uint32_t off = (uint32_t)m * PITCHB + (uint32_t)cp * 4;
            *(__half2*)(sm + SM_AH + off) = __half2{__float2half(v0), __float2half(v1)};
        }
    }
    if (tid < 128) {
        int t = t0 + tid;
        const float* xb = x + (size_t)b * (NCH * NT);
        *(float*)(sm + SM_X128 + tid * 4) = (t < NT) ? xb[(size_t)128 * NT + t] : 0.f;
        if (tid < TN) {
            *(float*)(sm + SM_W128 + tid * 4) = g_Wcol[jc * TN + tid];
            *(float*)(sm + SM_BIAS + tid * 4) = g_biasP[jc * TN + tid];
        }
    }
    __syncthreads();

    float acc[9][4];
    #pragma unroll
    for (int ni = 0; ni < 9; ni++)
        #pragma unroll
        for (int q = 0; q < 4; q++) acc[ni][q] = 0.f;

    const uint32_t aOff = (uint32_t)(wid * 16 + (lane & 15)) * PITCHB + (uint32_t)(lane >> 4) * 16;
    const uint32_t bOff = (uint32_t)(lane & 15) * PITCHB + (uint32_t)(lane >> 4) * 16;
    const uint32_t b2Off = (uint32_t)(64 + (lane & 7)) * PITCHB + (uint32_t)((lane >> 3) & 1) * 16;

    const uint32_t Ah = sbase + SM_AH + aOff;
    const uint32_t Bb = sbase + SM_BH + bOff;
    const uint32_t Bb2 = sbase + SM_BH + b2Off;

    #pragma unroll
    for (int kk = 0; kk < NKK; kk++) {
        uint32_t ah[4];
        ldsm4(ah, Ah + kk * 32);
        #pragma unroll
        for (int q = 0; q < 4; q++) {
            uint32_t bb[4];
            ldsm4(bb, Bb + (uint32_t)(q * 16) * PITCHB + kk * 32);
            uint32_t f0[2] = { bb[0], bb[2] };
            uint32_t f1[2] = { bb[1], bb[3] };
            mma16816(acc[2 * q],     ah, f0);
            mma16816(acc[2 * q + 1], ah, f1);
        }
        uint32_t b2[2];
        ldsm2(b2, Bb2 + kk * 32);
        mma16816(acc[8], ah, b2);
    }

    __syncthreads();
    float* stage = (float*)sm;
    {
        int r = wid * 16 + gid;
        #pragma unroll
        for (int ni = 0; ni < 9; ni++) {
            int c = ni * 8 + 2 * tig;
            *(float2*)(stage + r * SPITCH + c) = make_float2(acc[ni][0], acc[ni][1]);
            *(float2*)(stage + (r + 8) * SPITCH + c) = make_float2(acc[ni][2], acc[ni][3]);
        }
    }
    __syncthreads();

    const float* xs128 = (const float*)(sm + SM_X128);
    const float* sW = (const float*)(sm + SM_W128);
    const float* sBs = (const float*)(sm + SM_BIAS);
    for (int i = tid; i < TM * (TN / 4); i += 256) {
        int row = i / (TN / 4), q = i % (TN / 4);
        int t = t0 + row;
        int j = jc * TN + 4 * q;
        if (t < NT && j + 3 < DPROJ) {
            const float* sp = stage + row * SPITCH + 4 * q;
            float xk = xs128[row];
            float4 o;
            o.x = fmaf(xk, sW[4 * q + 0], sp[0] + sBs[4 * q + 0]);
            o.y = fmaf(xk, sW[4 * q + 1], sp[1] + sBs[4 * q + 1]);
            o.z = fmaf(xk, sW[4 * q + 2], sp[2] + sBs[4 * q + 2]);
            o.w = fmaf(xk, sW[4 * q + 3], sp[3] + sBs[4 * q + 3]);
            *(float4*)(g_zxbcdt + ((size_t)b * NT + t) * DPROJ + j) = o;
        }
    }
}

// =====================================================================
// scan: R5 version (measured 199us) — 160 threads, 2 channels/thread,
//       deferred RMSNorm, 1 barrier/step, direct out[b] write
// =====================================================================
__global__ void __launch_bounds__(160, 4)
scan_kernel(const float* __restrict__ conv_w, const float* __restrict__ conv_b,
            const float* __restrict__ dt_bias, const float* __restrict__ A_log,
            const float* __restrict__ Dp, const float* __restrict__ norm_w,
            const float* __restrict__ head_b, float* __restrict__ out) {
    const int b = blockIdx.x;
    const int tid = threadIdx.x;
    const int lane = tid & 31, wid = tid >> 5;
    const int c0 = 2 * tid;
    const int h = tid >> 5;

    __shared__ __align__(8) float2 sB2[2][DSTATE];
    __shared__ __align__(8) float2 sC2[2][DSTATE];
    __shared__ float sdA[2][NHEADS], sdt[2][NHEADS];
    __shared__ __align__(8) float2 sPS[NT][4];
    __shared__ float sfin[5];

    const bool isConv = (tid < 144);
    const bool isScan = (tid < 128);
    const bool isDt   = (tid >= 144 && tid < 148);

    ull wk2[4]; ull cb2 = 0ULL;
    if (isConv) {
        #pragma unroll
        for (int k = 0; k < 4; k++)
            wk2[k] = pack2(conv_w[c0 * 4 + k], conv_w[(c0 + 1) * 4 + k]);
        cb2 = pack2(conv_b[c0], conv_b[c0 + 1]);
    } else {
        wk2[0] = wk2[1] = wk2[2] = wk2[3] = 0ULL;
    }
    ull h1 = 0ULL, h2 = 0ULL, h3 = 0ULL;

    ull nw2 = 0ULL; float Dh = 0.f;
    if (isScan) {
        nw2 = pack2(norm_w[c0] * g_v[c0], norm_w[c0 + 1] * g_v[c0 + 1]);
        Dh = Dp[h];
    }
    float dtb = 0.f, Aneg = 0.f;
    if (isDt) { dtb = dt_bias[tid - 144]; Aneg = -expf(A_log[tid - 144]); }

    ull s2[DSTATE];
    #pragma unroll
    for (int n = 0; n < DSTATE; n++) s2[n] = 0ULL;

    const float* row = g_zxbcdt + (size_t)b * NT * DPROJ;

    ull raw2 = 0ULL; float2 z2 = make_float2(0.f, 0.f); float dtr = 0.f;
    if (isConv) raw2 = *(const ull*)(row + DINNER + c0);
    if (isScan) z2 = *(const float2*)(row + c0);
    if (isDt)   dtr = row[DPROJ - NHEADS + (tid - 144)];

    for (int t = 0; t < NT; t++) {
        const int buf = t & 1;

        float cs0 = 0.f, cs1 = 0.f;
        if (isConv) {
            ull cv2 = ffma2(wk2[3], raw2,
                      ffma2(wk2[2], h1,
                      ffma2(wk2[1], h2,
                      ffma2(wk2[0], h3, cb2))));
            h3 = h2; h2 = h1; h1 = raw2;
            float2 cv = unpk2(cv2);
            cs0 = __fdividef(cv.x, 1.f + __expf(-cv.x));
            cs1 = __fdividef(cv.y, 1.f + __expf(-cv.y));
            if (tid >= 128) {
                if (tid < 136) {
                    sB2[buf][2 * (tid - 128)]     = make_float2(cs0, cs0);
                    sB2[buf][2 * (tid - 128) + 1] = make_float2(cs1, cs1);
                } else {
                    sC2[buf][2 * (tid - 136)]     = make_float2(cs0, cs0);
                    sC2[buf][2 * (tid - 136) + 1] = make_float2(cs1, cs1);
                }
            }
        }
        if (isDt) {
            float rv = dtr + dtb;
            float dtv = (rv > 15.f) ? rv : __logf(1.f + __expf(rv));
            sdt[buf][tid - 144] = dtv;
            sdA[buf][tid - 144] = __expf(dtv * Aneg);
        }

        ull nraw2 = 0ULL; float2 nz2 = make_float2(0.f, 0.f); float ndtr = 0.f;
        if (t + 1 < NT) {
            const float* rn = row + (size_t)(t + 1) * DPROJ;
            if (isConv) nraw2 = *(const ull*)(rn + DINNER + c0);
            if (isScan) nz2 = *(const float2*)(rn + c0);
            if (isDt)   ndtr = rn[DPROJ - NHEADS + (tid - 144)];
        }
        __syncthreads();

        if (isScan) {
            float dtv = sdt[buf][h];
            ull dA2 = dup2(sdA[buf][h]);
            ull dx2 = pack2(dtv * cs0, dtv * cs1);
            ull y2 = 0ULL;
            #pragma unroll
            for (int n = 0; n < DSTATE; n++) {
                s2[n] = ffma2(s2[n], dA2, fmul2(dx2, *(const ull*)&sB2[buf][n]));
                y2 = ffma2(s2[n], *(const ull*)&sC2[buf][n], y2);
            }
            float2 yy = unpk2(y2);
            float y0 = fmaf(Dh, cs0, yy.x);
            float y1 = fmaf(Dh, cs1, yy.y);
            float g0 = y0 * __fdividef(z2.x, 1.f + __expf(-z2.x));
            float g1 = y1 * __fdividef(z2.y, 1.f + __expf(-z2.y));

            float ss = fmaf(g0, g0, g1 * g1);
            float p  = fmaf(g0, __uint_as_float((uint32_t)(nw2 & 0xffffffffu)),
                            g1 * __uint_as_float((uint32_t)(nw2 >> 32)));
            #pragma unroll
            for (int o = 16; o > 0; o >>= 1) {
                ss += __shfl_xor_sync(0xffffffffu, ss, o);
                p  += __shfl_xor_sync(0xffffffffu, p, o);
            }
            if (lane == 0) sPS[t][wid] = make_float2(ss, p);
        }

        raw2 = nraw2; z2 = nz2; dtr = ndtr;
    }

    // final phase: deferred rsqrt per timestep, accumulate
    __syncthreads();
    float facc = 0.f;
    for (int t = tid; t < NT; t += 160) {
        float2 a = sPS[t][0], b2 = sPS[t][1], c = sPS[t][2], d = sPS[t][3];
        float SS = (a.x + b2.x) + (c.x + d.x);
        float P  = (a.y + b2.y) + (c.y + d.y);
        facc = fmaf(P, rsqrtf(SS * (1.f / 256.f) + EPSV), facc);
    }
    #pragma unroll
    for (int o = 16; o > 0; o >>= 1) facc += __shfl_xor_sync(0xffffffffu, facc, o);
    if (lane == 0) sfin[wid] = facc;
    __syncthreads();
    if (tid == 0) {
        float tot = (sfin[0] + sfin[1]) + (sfin[2] + sfin[3]) + sfin[4];
        out[b] = tot * (1.f / (float)NT) + head_b[0];
    }
}

// =====================================================================
// launch
// =====================================================================
extern "C" void kernel_launch(void* const* d_in, const int* in_sizes, int n_in,
                              void* d_out, int out_size) {
    const float* x          = (const float*)d_in[0];
    const float* mixer_w    = (const float*)d_in[1];
    const float* mixer_b    = (const float*)d_in[2];
    const float* in_proj_w  = (const float*)d_in[3];
    const float* conv_w     = (const float*)d_in[4];
    const float* conv_b     = (const float*)d_in[5];
    const float* dt_bias    = (const float*)d_in[6];
    const float* A_log      = (const float*)d_in[7];
    const float* Dvec       = (const float*)d_in[8];
    const float* norm_w     = (const float*)d_in[9];
    const float* out_proj_w = (const float*)d_in[10];
    const float* head_w     = (const float*)d_in[11];
    const float* head_b     = (const float*)d_in[12];
    float* out = (float*)d_out;

    {
        int total = DPROJ * NCH + DPROJ + DINNER;
        prep1_kernel<<<(total + 255) / 256, 256>>>(in_proj_w, mixer_w, mixer_b,
                                                   out_proj_w, head_w);
    }
    {
        int total = NJC * TN * TK + 1152;
        prep2_kernel<<<(total + 255) / 256, 256>>>();
    }
    {
        cudaFuncSetAttribute(gemm_mma,
                             cudaFuncAttributeMaxDynamicSharedMemorySize, SMEM_SZ);
        dim3 grid(2, NJC, BSZ);
        gemm_mma<<<grid, 256, SMEM_SZ>>>(x);
    }
    scan_kernel<<<BSZ, 160>>>(conv_w, conv_b, dt_bias, A_log, Dvec,
                              norm_w, head_b, out);
}